// round 3
// baseline (speedup 1.0000x reference)
#include <cuda_runtime.h>

#define EMB_DIM 128
#define NB_WORDS 100000
#define MAX_BATCH 4096
#define RPT 8          // consecutive sorted rows per thread -> row hits per activate

// Scratch (allocation-free rule: __device__ globals)
__device__ int d_order[MAX_BATCH];  // sorted position -> original batch index
__device__ int d_sidx[MAX_BATCH];   // sorted position -> vocab index

// ---------------------------------------------------------------------------
// Kernel A: approximate counting sort of elt[] by (idx >> 6).
// 1 block, 1024 threads. 1563 bins padded to 2048 for the scan.
// ---------------------------------------------------------------------------
__global__ void order_kernel(const int* __restrict__ elt, int batch) {
    __shared__ int bufA[2048];
    __shared__ int bufB[2048];
    const int tid = threadIdx.x;

    for (int i = tid; i < 2048; i += 1024) bufA[i] = 0;
    __syncthreads();

    for (int b = tid; b < batch; b += 1024)
        atomicAdd(&bufA[elt[b] >> 6], 1);
    __syncthreads();

    // Hillis-Steele inclusive scan over 2048 bins (ping-pong)
    int* src = bufA;
    int* dst = bufB;
    for (int off = 1; off < 2048; off <<= 1) {
        for (int i = tid; i < 2048; i += 1024)
            dst[i] = src[i] + ((i >= off) ? src[i - off] : 0);
        __syncthreads();
        int* t = src; src = dst; dst = t;
    }
    // src now holds the inclusive scan; reuse dst as per-bin cursors
    for (int i = tid; i < 2048; i += 1024) dst[i] = 0;
    __syncthreads();

    for (int b = tid; b < batch; b += 1024) {
        const int idx = elt[b];
        const int bin = idx >> 6;
        const int base = (bin == 0) ? 0 : src[bin - 1];
        const int pos = base + atomicAdd(&dst[bin], 1);
        d_order[pos] = b;
        d_sidx[pos]  = idx;
    }
}

// ---------------------------------------------------------------------------
// Kernel B: gather in (approximately) sorted index order.
// 128 threads (one per embedding lane), RPT consecutive sorted rows each.
// Per lane e, the RPT gathers span a ~200-float window of W[e][*] -> DRAM row hits.
// ---------------------------------------------------------------------------
__global__ void gather_kernel(const float* __restrict__ W,
                              const float* __restrict__ bias,
                              float* __restrict__ out,
                              int batch) {
    const int e  = threadIdx.x;            // 0..127
    const int j0 = blockIdx.x * RPT;       // sorted position base

    const float bv = __ldg(&bias[e]);

    int b[RPT];
    int v[RPT];
    #pragma unroll
    for (int k = 0; k < RPT; k++) {
        const int j = j0 + k;
        b[k] = (j < batch) ? __ldg(&d_order[j]) : 0;
        v[k] = (j < batch) ? __ldg(&d_sidx[j])  : 0;
    }

    // Front-batched gathers: 8 independent loads, row-neighbors in DRAM.
    float w[RPT];
    #pragma unroll
    for (int k = 0; k < RPT; k++)
        w[k] = __ldcg(&W[(size_t)e * NB_WORDS + v[k]]);

    #pragma unroll
    for (int k = 0; k < RPT; k++) {
        const int j = j0 + k;
        if (j < batch)
            out[(size_t)b[k] * EMB_DIM + e] = w[k] + bv;
    }
}

extern "C" void kernel_launch(void* const* d_in, const int* in_sizes, int n_in,
                              void* d_out, int out_size) {
    const int* elt  = (const int*)d_in[0];
    const float* W  = (const float*)d_in[1];
    const float* bv = (const float*)d_in[2];
    float* out      = (float*)d_out;

    int batch = in_sizes[0];
    if (batch > MAX_BATCH) batch = MAX_BATCH;   // scratch bound (BATCH=4096 in spec)

    order_kernel<<<1, 1024>>>(elt, batch);
    const int blocks = (batch + RPT - 1) / RPT; // 512
    gather_kernel<<<blocks, EMB_DIM>>>(W, bv, out, batch);
}

// round 4
// speedup vs baseline: 1.2882x; 1.2882x over previous
#include <cuda_runtime.h>

#define EMB_DIM   128
#define NB_WORDS  100000
#define VC        200          // vocab columns per CTA chunk (100000 / 200 = 500 CTAs)
#define NCTA      (NB_WORDS / VC)
#define THREADS   256
#define LIST_CAP  1024         // expected matches/CTA ~8.2 (Poisson); 1024 is unreachable

// dynamic smem layout:
//   float Ws[128][VC]   (102400 B)  chunk of W, row-major, no pad
//   int   list[LIST_CAP] (4096 B)   packed matches: (b << 8) | col
//   int   cnt            (4 B)
#define SMEM_W_FLOATS (EMB_DIM * VC)
#define SMEM_BYTES    (SMEM_W_FLOATS * 4 + LIST_CAP * 4 + 4)

__global__ void __launch_bounds__(THREADS)
time_embedding_stream(const int* __restrict__ elt,
                      const float* __restrict__ W,
                      const float* __restrict__ bias,
                      float* __restrict__ out,
                      int batch) {
    extern __shared__ float smem[];
    float* Ws  = smem;                                   // [128][VC]
    int*  list = (int*)(smem + SMEM_W_FLOATS);
    int*  cnt  = list + LIST_CAP;

    const int tid = threadIdx.x;
    const int v0  = blockIdx.x * VC;

    if (tid == 0) *cnt = 0;

    // ---- Phase 1: stream W chunk [128 rows x VC cols] into smem (coalesced f4) ----
    // Global: row e, cols [v0, v0+VC). VC*4 = 800 B per row = 50 float4.
    // g indexes float4s: e = g / 50, c4 = g % 50. Consecutive tid -> consecutive
    // addresses within a row -> fully coalesced.
    constexpr int F4_PER_ROW  = VC / 4;                  // 50
    constexpr int F4_TOTAL    = EMB_DIM * F4_PER_ROW;    // 6400
    constexpr int F4_PER_THR  = F4_TOTAL / THREADS;      // 25

    #pragma unroll
    for (int k = 0; k < F4_PER_THR; k++) {
        const int g  = tid + k * THREADS;
        const int e  = g / F4_PER_ROW;
        const int c4 = g % F4_PER_ROW;
        const float4 v = __ldcs(
            (const float4*)(W + (size_t)e * NB_WORDS + v0 + c4 * 4));
        *(float4*)(Ws + e * VC + c4 * 4) = v;
    }

    // ---- Phase 2: scan elt for indices inside this chunk (L2-hot broadcast) ----
    for (int b = tid; b < batch; b += THREADS) {
        const int idx = __ldg(&elt[b]);
        const int col = idx - v0;
        if ((unsigned)col < (unsigned)VC) {
            const int p = atomicAdd(cnt, 1);
            if (p < LIST_CAP) list[p] = (b << 8) | col;
        }
    }

    const float bv = __ldg(&bias[tid & (EMB_DIM - 1)]);

    __syncthreads();   // Ws populated + list complete

    // ---- Phase 3: scatter matches. 2 groups of 128 threads, one match each. ----
    const int group = tid >> 7;          // 0 or 1
    const int e     = tid & (EMB_DIM - 1);
    const int n     = min(*cnt, LIST_CAP);

    for (int m = group; m < n; m += 2) {
        const int p   = list[m];
        const int b   = p >> 8;
        const int col = p & 255;
        out[(size_t)b * EMB_DIM + e] = Ws[e * VC + col] + bv;
    }
}

extern "C" void kernel_launch(void* const* d_in, const int* in_sizes, int n_in,
                              void* d_out, int out_size) {
    const int* elt  = (const int*)d_in[0];
    const float* W  = (const float*)d_in[1];
    const float* bv = (const float*)d_in[2];
    float* out      = (float*)d_out;
    const int batch = in_sizes[0];

    static bool attr_done = false;
    if (!attr_done) {
        cudaFuncSetAttribute(time_embedding_stream,
                             cudaFuncAttributeMaxDynamicSharedMemorySize,
                             SMEM_BYTES);
        attr_done = true;
    }

    time_embedding_stream<<<NCTA, THREADS, SMEM_BYTES>>>(elt, W, bv, out, batch);
}

// round 5
// speedup vs baseline: 1.8423x; 1.4301x over previous
#include <cuda_runtime.h>

#define EMB_DIM  128
#define NB_WORDS 100000
#define THREADS  256           // 2 row-groups of 128 lanes
#define BLOCKS   1184          // 8 blocks/SM x 148 SMs = exactly 2 full waves
#define RPT      2             // rows per thread, front-batched (MLP=2)

// out[b][e] = W[e * NB_WORDS + elt[b]] + bias[e]
__global__ void __launch_bounds__(THREADS)
time_embedding_kernel(const int* __restrict__ elt,
                      const float* __restrict__ W,
                      const float* __restrict__ bias,
                      float* __restrict__ out,
                      int batch) {
    const int e    = threadIdx.x & (EMB_DIM - 1);        // 0..127
    const int sub  = threadIdx.x >> 7;                   // 0..1
    const int slot = blockIdx.x * 2 + sub;               // 0..2367
    // Row k for this thread: slot + k * 2368 (keeps stores coalesced per group)
    const int STRIDE = BLOCKS * 2;                       // 2368

    const float bv = __ldg(&bias[e]);
    const float* Wrow = W + (size_t)e * NB_WORDS;

    // Front-batch index loads (warp-uniform broadcasts, L1/L2-hot)
    int b[RPT];
    int idx[RPT];
    #pragma unroll
    for (int k = 0; k < RPT; k++) {
        b[k] = slot + k * STRIDE;
        idx[k] = (b[k] < batch) ? __ldg(&elt[b[k]]) : 0;
    }

    // Front-batch the scattered gathers; .cg = L2-only (zero L1 reuse)
    float w[RPT];
    #pragma unroll
    for (int k = 0; k < RPT; k++)
        w[k] = __ldcg(&Wrow[idx[k]]);

    #pragma unroll
    for (int k = 0; k < RPT; k++) {
        if (b[k] < batch)
            __stcg(&out[(size_t)b[k] * EMB_DIM + e], w[k] + bv);
    }
}

extern "C" void kernel_launch(void* const* d_in, const int* in_sizes, int n_in,
                              void* d_out, int out_size) {
    const int* elt  = (const int*)d_in[0];
    const float* W  = (const float*)d_in[1];
    const float* bv = (const float*)d_in[2];
    float* out      = (float*)d_out;
    const int batch = in_sizes[0];   // 4096

    time_embedding_kernel<<<BLOCKS, THREADS>>>(elt, W, bv, out, batch);
}

// round 7
// speedup vs baseline: 1.9544x; 1.0608x over previous
#include <cuda_runtime.h>
#include <cstdint>

#define EMB_DIM  128
#define NB_WORDS 100000

// out[b][e] = W[e * NB_WORDS + elt[b]] + bias[e]
// R1 launch shape (best measured): 4 batch rows per 512-thread block.
__global__ void __launch_bounds__(512)
time_embedding_kernel(const int* __restrict__ elt,
                      const float* __restrict__ W,
                      const float* __restrict__ bias,
                      float* __restrict__ out,
                      int batch) {
    const int e   = threadIdx.x & (EMB_DIM - 1);   // 0..127
    const int sub = threadIdx.x >> 7;              // 0..3
    const int b   = blockIdx.x * 4 + sub;
    if (b >= batch) return;

    // Cache policies: W lines -> evict_last (pin in L2 across graph replays),
    // output lines -> evict_first (streaming, never displace W).
    uint64_t pol_last, pol_first;
    asm volatile("createpolicy.fractional.L2::evict_last.b64 %0, 1.0;"
                 : "=l"(pol_last));
    asm volatile("createpolicy.fractional.L2::evict_first.b64 %0, 1.0;"
                 : "=l"(pol_first));

    const int idx = __ldg(&elt[b]);                // warp-uniform broadcast
    const float* wp = &W[(size_t)e * NB_WORDS + idx];

    float w;
    asm volatile("ld.global.nc.L2::cache_hint.f32 %0, [%1], %2;"
                 : "=f"(w) : "l"(wp), "l"(pol_last));

    const float bv = __ldg(&bias[e]);
    float* op = &out[(size_t)b * EMB_DIM + e];
    const float val = w + bv;
    asm volatile("st.global.L2::cache_hint.f32 [%0], %1, %2;"
                 :: "l"(op), "f"(val), "l"(pol_first) : "memory");
}

extern "C" void kernel_launch(void* const* d_in, const int* in_sizes, int n_in,
                              void* d_out, int out_size) {
    const int* elt  = (const int*)d_in[0];
    const float* W  = (const float*)d_in[1];
    const float* bv = (const float*)d_in[2];
    float* out      = (float*)d_out;
    const int batch = in_sizes[0];                 // 4096

    time_embedding_kernel<<<(batch + 3) / 4, 512>>>(elt, W, bv, out, batch);
}